// round 14
// baseline (speedup 1.0000x reference)
#include <cuda_runtime.h>
#include <cuda_bf16.h>
#include <math.h>
#include <stdint.h>

#define NMAX 100000
#define EMAX 1600000
#define D_IN 512
#define D_H  128
#define D_OUT 40
#define SCAN_B 512

// ================= scratch (static device globals; no dynamic alloc) ===========
__device__ int      g_cnt[NMAX];
__device__ int      g_local[NMAX];
__device__ int      g_partials[512];
__device__ int      g_row_ptr[NMAX + 1];
__device__ int      g_cursor[NMAX];
__device__ int      g_col[EMAX];
__device__ float    g_dinv[NMAX];
// h1 stored as packed bf16x2 (row = 64 u32 words) — only consumed by agg1
__device__ uint32_t g_h1b[NMAX * 64];
__device__ float    g_h2 [NMAX * D_OUT];
// h1a (post agg+relu) pre-split bf16 hi/lo, packed 2 per u32, row = 64 u32
__device__ uint32_t g_h1h[NMAX * 64];
__device__ uint32_t g_h1l[NMAX * 64];
// W1 split bf16 hi/lo in mma-fragment-packed order:
//   [K=32 k16-blocks][N2=8 n16-blocks][lane=32] uint4
__device__ uint4    g_w1f_h[32 * 8 * 32];
__device__ uint4    g_w1f_l[32 * 8 * 32];
// W2 split bf16 hi/lo, [k=128][n=56 padded] as u32 words [128][28]
__device__ uint32_t g_w2h[128 * 28];
__device__ uint32_t g_w2l[128 * 28];

// ================= small helpers ================================================
__device__ __forceinline__ uint32_t smem_u32(const void* p) {
    uint32_t a;
    asm("{ .reg .u64 t; cvta.to.shared.u64 t, %1; cvt.u32.u64 %0, t; }" : "=r"(a) : "l"(p));
    return a;
}
__device__ __forceinline__ uint32_t pack_hi(float2 p) {
    uint32_t r;
    asm("cvt.rn.bf16x2.f32 %0, %1, %2;" : "=r"(r) : "f"(p.y), "f"(p.x));
    return r;
}
__device__ __forceinline__ uint32_t pack_lo(float2 p, uint32_t h) {
    float fx = __uint_as_float(h << 16);
    float fy = __uint_as_float(h & 0xffff0000u);
    uint32_t r;
    asm("cvt.rn.bf16x2.f32 %0, %1, %2;" : "=r"(r) : "f"(p.y - fy), "f"(p.x - fx));
    return r;
}
__device__ __forceinline__ float2 bf2f(uint32_t u) {
    __nv_bfloat162 h = *reinterpret_cast<__nv_bfloat162*>(&u);
    return __bfloat1622float2(h);
}

// ldmatrix x2 trans (B, [k][n] row-major stride 56; one n8 tile, k16) — gemm2 only
__device__ __forceinline__ void ldmB56x2(uint32_t* d, const uint16_t* sm, int kk, int n0, int lane) {
    uint32_t addr = smem_u32(sm + (kk + (lane & 15)) * 56 + n0);
    asm volatile("ldmatrix.sync.aligned.m8n8.x2.trans.shared.b16 {%0,%1}, [%2];"
                 : "=r"(d[0]), "=r"(d[1]) : "r"(addr) : "memory");
}
// NOT volatile: pure arithmetic; ptxas may pipeline freely.
__device__ __forceinline__ void mma_bf16(float* c, const uint32_t* a, uint32_t b0, uint32_t b1) {
    asm("mma.sync.aligned.m16n8k16.row.col.f32.bf16.bf16.f32 "
        "{%0,%1,%2,%3}, {%4,%5,%6,%7}, {%8,%9}, {%0,%1,%2,%3};"
        : "+f"(c[0]), "+f"(c[1]), "+f"(c[2]), "+f"(c[3])
        : "r"(a[0]), "r"(a[1]), "r"(a[2]), "r"(a[3]), "r"(b0), "r"(b1));
}

// ---------------- degree / CSR build -------------------------------------------
__global__ void zero_cnt_kernel(int n) {
    int i = blockIdx.x * blockDim.x + threadIdx.x;
    if (i < n) g_cnt[i] = 0;
}
__global__ void count_kernel(const int* __restrict__ dst, int e_cnt) {
    int e = blockIdx.x * blockDim.x + threadIdx.x;
    if (e < e_cnt) atomicAdd(&g_cnt[dst[e]], 1);
}
__global__ void scan_block_kernel(int n) {
    __shared__ int sh[SCAN_B];
    int i = blockIdx.x * SCAN_B + threadIdx.x;
    int v = (i < n) ? g_cnt[i] : 0;
    sh[threadIdx.x] = v;
    __syncthreads();
    #pragma unroll
    for (int off = 1; off < SCAN_B; off <<= 1) {
        int t = 0;
        if ((int)threadIdx.x >= off) t = sh[threadIdx.x - off];
        __syncthreads();
        sh[threadIdx.x] += t;
        __syncthreads();
    }
    if (i < n) g_local[i] = sh[threadIdx.x] - v;
    if (threadIdx.x == SCAN_B - 1) g_partials[blockIdx.x] = sh[SCAN_B - 1];
}
__global__ void scan_partials_kernel(int nb) {
    __shared__ int sh[512];
    int t = threadIdx.x;
    int v = (t < nb) ? g_partials[t] : 0;
    sh[t] = v;
    __syncthreads();
    #pragma unroll
    for (int off = 1; off < 512; off <<= 1) {
        int tv = 0;
        if (t >= off) tv = sh[t - off];
        __syncthreads();
        sh[t] += tv;
        __syncthreads();
    }
    if (t < nb) g_partials[t] = sh[t] - v;
}
__global__ void scan_add_kernel(int n, int e_cnt) {
    int i = blockIdx.x * SCAN_B + threadIdx.x;
    if (i < n) {
        int r = g_local[i] + g_partials[blockIdx.x];
        g_row_ptr[i] = r;
        g_cursor[i]  = r;
        g_dinv[i] = rsqrtf((float)(g_cnt[i] + 1));
    }
    if (i == 0) g_row_ptr[n] = e_cnt;
}
__global__ void fill_csr_kernel(const int* __restrict__ src,
                                const int* __restrict__ dst, int e_cnt) {
    int e = blockIdx.x * blockDim.x + threadIdx.x;
    if (e < e_cnt) {
        int d = dst[e];
        int pos = atomicAdd(&g_cursor[d], 1);
        g_col[pos] = src[e];
    }
}

// ---------------- prep: W1 -> fragment-packed split bf16; W2 -> padded split ----
__global__ void prep_kernel(const float* __restrict__ W1, const float* __restrict__ W2) {
    int i = blockIdx.x * blockDim.x + threadIdx.x;
    if (i < 32 * 8 * 32) {
        int lane = i & 31;
        int N2   = (i >> 5) & 7;
        int K    = i >> 8;
        int t = lane & 3, g = lane >> 2;
        int k0 = K * 16 + 2 * t;
        int n  = N2 * 16 + g;
        float2 p0 = make_float2(W1[(k0    ) * D_H + n],     W1[(k0 + 1) * D_H + n]);
        float2 p1 = make_float2(W1[(k0 + 8) * D_H + n],     W1[(k0 + 9) * D_H + n]);
        float2 p2 = make_float2(W1[(k0    ) * D_H + n + 8], W1[(k0 + 1) * D_H + n + 8]);
        float2 p3 = make_float2(W1[(k0 + 8) * D_H + n + 8], W1[(k0 + 9) * D_H + n + 8]);
        uint4 h, l;
        h.x = pack_hi(p0); l.x = pack_lo(p0, h.x);
        h.y = pack_hi(p1); l.y = pack_lo(p1, h.y);
        h.z = pack_hi(p2); l.z = pack_lo(p2, h.z);
        h.w = pack_hi(p3); l.w = pack_lo(p3, h.w);
        g_w1f_h[i] = h;
        g_w1f_l[i] = l;
    } else {
        int j = i - 32 * 8 * 32;
        if (j < 128 * 28) {
            int k = j / 28, c = j % 28;
            float2 p;
            p.x = (2 * c     < D_OUT) ? W2[k * D_OUT + 2 * c]     : 0.f;
            p.y = (2 * c + 1 < D_OUT) ? W2[k * D_OUT + 2 * c + 1] : 0.f;
            uint32_t hp = pack_hi(p);
            g_w2h[j] = hp;
            g_w2l[j] = pack_lo(p, hp);
        }
    }
}

// ---------------- GEMM1 (HMMA): h1 = x @ W1 -------------------------------------
// Occupancy-optimized: block 64 rows x 128 cols, 8 warps (4m x 2n),
// warp tile 16x64 -> ~80 regs -> 3 CTAs/SM = 6 warps/SMSP.
// Sync-free, smem-free; A prefetched one iteration ahead; B hi->lo through
// one 16-reg buffer. bf16x2-packed epilogue.
__global__ __launch_bounds__(256, 3) void gemm1_mma_kernel(const float* __restrict__ A, int M) {
    const int tid  = threadIdx.x;
    const int lane = tid & 31;
    const int wid  = tid >> 5;
    const int wm   = wid >> 1;     // 0..3 (16-row group)
    const int wn   = wid & 1;      // 0..1 (64-col group)
    const int row0 = blockIdx.x * 64;

    const int fr = row0 + wm * 16 + (lane >> 2);
    const int fc = (lane & 3) * 2;
    const float* pr[2];
    bool vr[2];
    #pragma unroll
    for (int h = 0; h < 2; h++) {
        int r = fr + h * 8;
        vr[h] = (r < M);
        pr[h] = A + (size_t)(vr[h] ? r : 0) * D_IN;
    }

    const uint4* bfh = g_w1f_h + (size_t)(wn * 4) * 32 + lane;
    const uint4* bfl = g_w1f_l + (size_t)(wn * 4) * 32 + lane;

    float acc[8][4];
    #pragma unroll
    for (int b = 0; b < 8; b++)
        #pragma unroll
        for (int c = 0; c < 4; c++) acc[b][c] = 0.f;

    const float2 z2 = make_float2(0.f, 0.f);

    // prologue: A loads for K=0
    float2 p[4];
    p[0] = vr[0] ? *(const float2*)&pr[0][fc]     : z2;
    p[1] = vr[1] ? *(const float2*)&pr[1][fc]     : z2;
    p[2] = vr[0] ? *(const float2*)&pr[0][fc + 8] : z2;
    p[3] = vr[1] ? *(const float2*)&pr[1][fc + 8] : z2;

    for (int K = 0; K < 32; K++) {
        uint32_t ah[4], al[4];
        #pragma unroll
        for (int j = 0; j < 4; j++) {
            ah[j] = pack_hi(p[j]);
            al[j] = pack_lo(p[j], ah[j]);
        }
        if (K < 31) {
            const int c = (K + 1) * 16 + fc;
            p[0] = vr[0] ? *(const float2*)&pr[0][c]     : z2;
            p[1] = vr[1] ? *(const float2*)&pr[1][c]     : z2;
            p[2] = vr[0] ? *(const float2*)&pr[0][c + 8] : z2;
            p[3] = vr[1] ? *(const float2*)&pr[1][c + 8] : z2;
        }

        // B hi pass: 16 MMAs (ah + al)
        uint4 q[4];
        #pragma unroll
        for (int j = 0; j < 4; j++) q[j] = bfh[(size_t)(K * 8 + j) * 32];
        #pragma unroll
        for (int j = 0; j < 4; j++) {
            mma_bf16(acc[2*j],     ah, q[j].x, q[j].y);
            mma_bf16(acc[2*j + 1], ah, q[j].z, q[j].w);
        }
        #pragma unroll
        for (int j = 0; j < 4; j++) {
            mma_bf16(acc[2*j],     al, q[j].x, q[j].y);
            mma_bf16(acc[2*j + 1], al, q[j].z, q[j].w);
        }
        // B lo pass: 8 MMAs (ah only)
        #pragma unroll
        for (int j = 0; j < 4; j++) q[j] = bfl[(size_t)(K * 8 + j) * 32];
        #pragma unroll
        for (int j = 0; j < 4; j++) {
            mma_bf16(acc[2*j],     ah, q[j].x, q[j].y);
            mma_bf16(acc[2*j + 1], ah, q[j].z, q[j].w);
        }
    }

    // epilogue: pack pairs to bf16x2, one u32 per (row, n8 tile)
    const int g  = lane >> 2;
    const int tg = lane & 3;
    #pragma unroll
    for (int nt = 0; nt < 8; nt++) {
        int word = (wn * 4 + (nt >> 1)) * 8 + (nt & 1) * 4 + tg;
        int r0 = row0 + wm * 16 + g;
        if (r0 < M)
            g_h1b[(size_t)r0 * 64 + word] =
                pack_hi(make_float2(acc[nt][0], acc[nt][1]));
        int r1 = r0 + 8;
        if (r1 < M)
            g_h1b[(size_t)r1 * 64 + word] =
                pack_hi(make_float2(acc[nt][2], acc[nt][3]));
    }
}

// ---------------- Aggregation layer 1: warp per node, bf16 gathers, MLP-4 ------
__global__ void agg1_kernel(const float* __restrict__ b1, int n) {
    int warp = (blockIdx.x * blockDim.x + threadIdx.x) >> 5;
    int lane = threadIdx.x & 31;
    if (warp >= n) return;
    const int node = warp;
    const int start = g_row_ptr[node];
    const int end   = g_row_ptr[node + 1];
    const int cw = lane * 2;   // u32 word offset within 64-word row

    float4 a0 = make_float4(0.f,0.f,0.f,0.f), a1 = a0, a2 = a0, a3 = a0;
    int e = start;
    while (e < end && (e & 3)) {
        int s = g_col[e];
        float d = g_dinv[s];
        uint2 w = *(const uint2*)&g_h1b[(size_t)s * 64 + cw];
        float2 f0 = bf2f(w.x), f1 = bf2f(w.y);
        a0.x = fmaf(d, f0.x, a0.x); a0.y = fmaf(d, f0.y, a0.y);
        a0.z = fmaf(d, f1.x, a0.z); a0.w = fmaf(d, f1.y, a0.w);
        e++;
    }
    for (; e + 4 <= end; e += 4) {
        int4 cs = *(const int4*)&g_col[e];
        float d0 = g_dinv[cs.x], d1 = g_dinv[cs.y], d2 = g_dinv[cs.z], d3 = g_dinv[cs.w];
        uint2 w0 = *(const uint2*)&g_h1b[(size_t)cs.x * 64 + cw];
        uint2 w1 = *(const uint2*)&g_h1b[(size_t)cs.y * 64 + cw];
        uint2 w2 = *(const uint2*)&g_h1b[(size_t)cs.z * 64 + cw];
        uint2 w3 = *(const uint2*)&g_h1b[(size_t)cs.w * 64 + cw];
        float2 f;
        f = bf2f(w0.x); a0.x = fmaf(d0, f.x, a0.x); a0.y = fmaf(d0, f.y, a0.y);
        f = bf2f(w0.y); a0.z = fmaf(d0, f.x, a0.z); a0.w = fmaf(d0, f.y, a0.w);
        f = bf2f(w1.x); a1.x = fmaf(d1, f.x, a1.x); a1.y = fmaf(d1, f.y, a1.y);
        f = bf2f(w1.y); a1.z = fmaf(d1, f.x, a1.z); a1.w = fmaf(d1, f.y, a1.w);
        f = bf2f(w2.x); a2.x = fmaf(d2, f.x, a2.x); a2.y = fmaf(d2, f.y, a2.y);
        f = bf2f(w2.y); a2.z = fmaf(d2, f.x, a2.z); a2.w = fmaf(d2, f.y, a2.w);
        f = bf2f(w3.x); a3.x = fmaf(d3, f.x, a3.x); a3.y = fmaf(d3, f.y, a3.y);
        f = bf2f(w3.y); a3.z = fmaf(d3, f.x, a3.z); a3.w = fmaf(d3, f.y, a3.w);
    }
    for (; e < end; e++) {
        int s = g_col[e];
        float d = g_dinv[s];
        uint2 w = *(const uint2*)&g_h1b[(size_t)s * 64 + cw];
        float2 f0 = bf2f(w.x), f1 = bf2f(w.y);
        a0.x = fmaf(d, f0.x, a0.x); a0.y = fmaf(d, f0.y, a0.y);
        a0.z = fmaf(d, f1.x, a0.z); a0.w = fmaf(d, f1.y, a0.w);
    }
    float4 acc;
    acc.x = (a0.x + a1.x) + (a2.x + a3.x);
    acc.y = (a0.y + a1.y) + (a2.y + a3.y);
    acc.z = (a0.z + a1.z) + (a2.z + a3.z);
    acc.w = (a0.w + a1.w) + (a2.w + a3.w);

    float di = g_dinv[node];
    uint2 ws = *(const uint2*)&g_h1b[(size_t)node * 64 + cw];
    float2 s0 = bf2f(ws.x), s1 = bf2f(ws.y);
    float4 bb = *(const float4*)&b1[lane << 2];
    float4 o;
    o.x = fmaxf(fmaf(di, fmaf(di, s0.x, acc.x), bb.x), 0.f);
    o.y = fmaxf(fmaf(di, fmaf(di, s0.y, acc.y), bb.y), 0.f);
    o.z = fmaxf(fmaf(di, fmaf(di, s1.x, acc.z), bb.z), 0.f);
    o.w = fmaxf(fmaf(di, fmaf(di, s1.y, acc.w), bb.w), 0.f);

    float2 pa = make_float2(o.x, o.y), pb = make_float2(o.z, o.w);
    uint32_t ha = pack_hi(pa), hb = pack_hi(pb);
    uint2 hp = make_uint2(ha, hb);
    uint2 lp = make_uint2(pack_lo(pa, ha), pack_lo(pb, hb));
    *(uint2*)&g_h1h[(size_t)node * 64 + cw] = hp;
    *(uint2*)&g_h1l[(size_t)node * 64 + cw] = lp;
}

// ---------------- GEMM2 (HMMA): h2 = h1a @ W2 -----------------------------------
__global__ __launch_bounds__(256) void gemm2_mma_kernel(int M) {
    __shared__ __align__(16) uint16_t Bh[128 * 56];
    __shared__ __align__(16) uint16_t Bl[128 * 56];
    const int tid  = threadIdx.x;
    const int lane = tid & 31;
    const int wid  = tid >> 5;
    const int row0 = blockIdx.x * 128;

    uint32_t* Bh32 = reinterpret_cast<uint32_t*>(Bh);
    uint32_t* Bl32 = reinterpret_cast<uint32_t*>(Bl);
    for (int idx = tid; idx < 128 * 28; idx += 256) {
        int k = idx / 28, j = idx % 28;
        Bh32[k * 28 + j] = g_w2h[idx];
        Bl32[k * 28 + j] = g_w2l[idx];
    }
    __syncthreads();

    const int r0 = row0 + wid * 16 + (lane >> 2);
    const int r1 = r0 + 8;
    const bool v0 = (r0 < M), v1 = (r1 < M);
    const uint32_t* ph0 = g_h1h + (size_t)(v0 ? r0 : 0) * 64;
    const uint32_t* ph1 = g_h1h + (size_t)(v1 ? r1 : 0) * 64;
    const uint32_t* pl0 = g_h1l + (size_t)(v0 ? r0 : 0) * 64;
    const uint32_t* pl1 = g_h1l + (size_t)(v1 ? r1 : 0) * 64;

    float acc[5][4];
    #pragma unroll
    for (int a = 0; a < 5; a++)
        #pragma unroll
        for (int c = 0; c < 4; c++) acc[a][c] = 0.f;

    #pragma unroll
    for (int kk = 0; kk < 128; kk += 16) {
        const int kw = (kk >> 1) + (lane & 3);
        uint32_t ah[4], al[4];
        ah[0] = v0 ? ph0[kw]     : 0u;
        ah[1] = v1 ? ph1[kw]     : 0u;
        ah[2] = v0 ? ph0[kw + 4] : 0u;
        ah[3] = v1 ? ph1[kw + 4] : 0u;
        al[0] = v0 ? pl0[kw]     : 0u;
        al[1] = v1 ? pl1[kw]     : 0u;
        al[2] = v0 ? pl0[kw + 4] : 0u;
        al[3] = v1 ? pl1[kw + 4] : 0u;
        #pragma unroll
        for (int nt = 0; nt < 5; nt++) {
            uint32_t bh[2], bl[2];
            ldmB56x2(bh, Bh, kk, nt * 8, lane);
            ldmB56x2(bl, Bl, kk, nt * 8, lane);
            mma_bf16(acc[nt], ah, bh[0], bh[1]);
            mma_bf16(acc[nt], ah, bl[0], bl[1]);
            mma_bf16(acc[nt], al, bh[0], bh[1]);
        }
    }

    const int g  = lane >> 2;
    const int tg = lane & 3;
    #pragma unroll
    for (int nt = 0; nt < 5; nt++) {
        int col = nt * 8 + tg * 2;
        if (v0)
            *(float2*)&g_h2[(size_t)r0 * D_OUT + col] = make_float2(acc[nt][0], acc[nt][1]);
        if (v1)
            *(float2*)&g_h2[(size_t)r1 * D_OUT + col] = make_float2(acc[nt][2], acc[nt][3]);
    }
}

// ---------------- Aggregation layer 2 + bias + log_softmax (MLP-4) -------------
__global__ void agg2_kernel(const float* __restrict__ b2, float* __restrict__ out, int n) {
    int warp = (blockIdx.x * blockDim.x + threadIdx.x) >> 5;
    int lane = threadIdx.x & 31;
    if (warp >= n) return;
    const int node = warp;
    const int start = g_row_ptr[node];
    const int end   = g_row_ptr[node + 1];
    const bool hi = (lane < 8);

    float p0 = 0.f, p1 = 0.f, p2 = 0.f, p3 = 0.f;
    float q0 = 0.f, q1 = 0.f, q2 = 0.f, q3 = 0.f;
    int e = start;
    while (e < end && (e & 3)) {
        int s = g_col[e];
        float d = g_dinv[s];
        const float* hp = &g_h2[(size_t)s * D_OUT];
        p0 = fmaf(d, hp[lane], p0);
        if (hi) q0 = fmaf(d, hp[lane + 32], q0);
        e++;
    }
    for (; e + 4 <= end; e += 4) {
        int4 cs = *(const int4*)&g_col[e];
        float d0 = g_dinv[cs.x], d1 = g_dinv[cs.y], d2 = g_dinv[cs.z], d3 = g_dinv[cs.w];
        const float* h0p = &g_h2[(size_t)cs.x * D_OUT];
        const float* h1p = &g_h2[(size_t)cs.y * D_OUT];
        const float* h2p = &g_h2[(size_t)cs.z * D_OUT];
        const float* h3p = &g_h2[(size_t)cs.w * D_OUT];
        p0 = fmaf(d0, h0p[lane], p0); p1 = fmaf(d1, h1p[lane], p1);
        p2 = fmaf(d2, h2p[lane], p2); p3 = fmaf(d3, h3p[lane], p3);
        if (hi) {
            q0 = fmaf(d0, h0p[lane + 32], q0); q1 = fmaf(d1, h1p[lane + 32], q1);
            q2 = fmaf(d2, h2p[lane + 32], q2); q3 = fmaf(d3, h3p[lane + 32], q3);
        }
    }
    for (; e < end; e++) {
        int s = g_col[e];
        float d = g_dinv[s];
        const float* hp = &g_h2[(size_t)s * D_OUT];
        p0 = fmaf(d, hp[lane], p0);
        if (hi) q0 = fmaf(d, hp[lane + 32], q0);
    }
    float acc0 = (p0 + p1) + (p2 + p3);
    float acc1 = (q0 + q1) + (q2 + q3);

    float di = g_dinv[node];
    const float* sp = &g_h2[(size_t)node * D_OUT];
    float v0 = fmaf(di, fmaf(di, sp[lane], acc0), b2[lane]);
    float v1 = 0.f;
    if (hi) v1 = fmaf(di, fmaf(di, sp[lane + 32], acc1), b2[lane + 32]);

    float m = hi ? fmaxf(v0, v1) : v0;
    #pragma unroll
    for (int o = 16; o >= 1; o >>= 1)
        m = fmaxf(m, __shfl_xor_sync(0xffffffffu, m, o));
    float s = expf(v0 - m) + (hi ? expf(v1 - m) : 0.f);
    #pragma unroll
    for (int o = 16; o >= 1; o >>= 1)
        s += __shfl_xor_sync(0xffffffffu, s, o);
    float ls = logf(s);

    out[node * D_OUT + lane] = v0 - m - ls;
    if (hi) out[node * D_OUT + 32 + lane] = v1 - m - ls;
}

// ---------------- launch --------------------------------------------------------
extern "C" void kernel_launch(void* const* d_in, const int* in_sizes, int n_in,
                              void* d_out, int out_size) {
    const float* x   = (const float*)d_in[0];
    const int*   ei  = (const int*)d_in[1];    // edge_index is int32 (JAX x64 disabled)
    const float* W1  = (const float*)d_in[2];
    const float* b1  = (const float*)d_in[3];
    const float* W2  = (const float*)d_in[4];
    const float* b2  = (const float*)d_in[5];
    float* out = (float*)d_out;

    const int n = in_sizes[0] / D_IN;   // 100000
    const int e = in_sizes[1] / 2;      // 1600000
    const int* src = ei;
    const int* dst = ei + e;

    const int nb_scan = (n + SCAN_B - 1) / SCAN_B;

    static cudaStream_t s_csr = nullptr;
    static cudaEvent_t ev_fork = nullptr, ev_join = nullptr;
    if (s_csr == nullptr) {
        cudaStreamCreateWithFlags(&s_csr, cudaStreamNonBlocking);
        cudaEventCreateWithFlags(&ev_fork, cudaEventDisableTiming);
        cudaEventCreateWithFlags(&ev_join, cudaEventDisableTiming);
    }

    cudaEventRecord(ev_fork, 0);
    cudaStreamWaitEvent(s_csr, ev_fork, 0);

    // gemm1 stays 4th launch (ncu profiles that slot)
    prep_kernel<<<(32 * 8 * 32 + 128 * 28 + 255) / 256, 256>>>(W1, W2);          // 1
    zero_cnt_kernel<<<(n + 255) / 256, 256, 0, s_csr>>>(n);                       // 2
    count_kernel<<<(e + 255) / 256, 256, 0, s_csr>>>(dst, e);                     // 3
    gemm1_mma_kernel<<<(n + 63) / 64, 256>>>(x, n);                               // 4
    scan_block_kernel<<<nb_scan, SCAN_B, 0, s_csr>>>(n);                          // 5
    scan_partials_kernel<<<1, 512, 0, s_csr>>>(nb_scan);                          // 6
    scan_add_kernel<<<nb_scan, SCAN_B, 0, s_csr>>>(n, e);                         // 7
    fill_csr_kernel<<<(e + 255) / 256, 256, 0, s_csr>>>(src, dst, e);             // 8
    cudaEventRecord(ev_join, s_csr);

    cudaStreamWaitEvent(0, ev_join, 0);

    agg1_kernel<<<(n * 32 + 255) / 256, 256>>>(b1, n);
    gemm2_mma_kernel<<<(n + 127) / 128, 256>>>(n);
    agg2_kernel<<<(n * 32 + 255) / 256, 256>>>(b2, out, n);
}

// round 16
// speedup vs baseline: 1.1088x; 1.1088x over previous
#include <cuda_runtime.h>
#include <cuda_bf16.h>
#include <math.h>
#include <stdint.h>

#define NMAX 100000
#define EMAX 1600000
#define D_IN 512
#define D_H  128
#define D_OUT 40
#define SCAN_B 512

// ================= scratch (static device globals; no dynamic alloc) ===========
__device__ int      g_cnt[NMAX];
__device__ int      g_local[NMAX];
__device__ int      g_partials[512];
__device__ int      g_row_ptr[NMAX + 1];
__device__ int      g_cursor[NMAX];
__device__ int      g_col[EMAX];
__device__ float    g_dinv[NMAX];
// h1 stored as packed bf16x2 (row = 64 u32 words) — only consumed by agg1
__device__ uint32_t g_h1b[NMAX * 64];
__device__ float    g_h2 [NMAX * D_OUT];
// h1a (post agg+relu) pre-split bf16 hi/lo, packed 2 per u32, row = 64 u32
__device__ uint32_t g_h1h[NMAX * 64];
__device__ uint32_t g_h1l[NMAX * 64];
// W1 split bf16 hi/lo in mma-fragment-packed order:
//   [K=32 k16-blocks][N2=8 n16-blocks][lane=32] uint4
__device__ uint4    g_w1f_h[32 * 8 * 32];
__device__ uint4    g_w1f_l[32 * 8 * 32];
// W2 split bf16 hi/lo, [k=128][n=56 padded] as u32 words [128][28]
__device__ uint32_t g_w2h[128 * 28];
__device__ uint32_t g_w2l[128 * 28];

// ================= small helpers ================================================
__device__ __forceinline__ uint32_t smem_u32(const void* p) {
    uint32_t a;
    asm("{ .reg .u64 t; cvta.to.shared.u64 t, %1; cvt.u32.u64 %0, t; }" : "=r"(a) : "l"(p));
    return a;
}
__device__ __forceinline__ uint32_t pack_hi(float2 p) {
    uint32_t r;
    asm("cvt.rn.bf16x2.f32 %0, %1, %2;" : "=r"(r) : "f"(p.y), "f"(p.x));
    return r;
}
__device__ __forceinline__ uint32_t pack_lo(float2 p, uint32_t h) {
    float fx = __uint_as_float(h << 16);
    float fy = __uint_as_float(h & 0xffff0000u);
    uint32_t r;
    asm("cvt.rn.bf16x2.f32 %0, %1, %2;" : "=r"(r) : "f"(p.y - fy), "f"(p.x - fx));
    return r;
}
__device__ __forceinline__ float2 bf2f(uint32_t u) {
    __nv_bfloat162 h = *reinterpret_cast<__nv_bfloat162*>(&u);
    return __bfloat1622float2(h);
}

// ldmatrix x2 trans (B, [k][n] row-major stride 56; one n8 tile, k16) — gemm2 only
__device__ __forceinline__ void ldmB56x2(uint32_t* d, const uint16_t* sm, int kk, int n0, int lane) {
    uint32_t addr = smem_u32(sm + (kk + (lane & 15)) * 56 + n0);
    asm volatile("ldmatrix.sync.aligned.m8n8.x2.trans.shared.b16 {%0,%1}, [%2];"
                 : "=r"(d[0]), "=r"(d[1]) : "r"(addr) : "memory");
}
// NOT volatile: pure arithmetic; ptxas may pipeline freely.
__device__ __forceinline__ void mma_bf16(float* c, const uint32_t* a, uint32_t b0, uint32_t b1) {
    asm("mma.sync.aligned.m16n8k16.row.col.f32.bf16.bf16.f32 "
        "{%0,%1,%2,%3}, {%4,%5,%6,%7}, {%8,%9}, {%0,%1,%2,%3};"
        : "+f"(c[0]), "+f"(c[1]), "+f"(c[2]), "+f"(c[3])
        : "r"(a[0]), "r"(a[1]), "r"(a[2]), "r"(a[3]), "r"(b0), "r"(b1));
}

// ---------------- degree / CSR build -------------------------------------------
__global__ void zero_cnt_kernel(int n) {
    int i = blockIdx.x * blockDim.x + threadIdx.x;
    if (i < n) g_cnt[i] = 0;
}
__global__ void count_kernel(const int* __restrict__ dst, int e_cnt) {
    int e = blockIdx.x * blockDim.x + threadIdx.x;
    if (e < e_cnt) atomicAdd(&g_cnt[dst[e]], 1);
}
__global__ void scan_block_kernel(int n) {
    __shared__ int sh[SCAN_B];
    int i = blockIdx.x * SCAN_B + threadIdx.x;
    int v = (i < n) ? g_cnt[i] : 0;
    sh[threadIdx.x] = v;
    __syncthreads();
    #pragma unroll
    for (int off = 1; off < SCAN_B; off <<= 1) {
        int t = 0;
        if ((int)threadIdx.x >= off) t = sh[threadIdx.x - off];
        __syncthreads();
        sh[threadIdx.x] += t;
        __syncthreads();
    }
    if (i < n) g_local[i] = sh[threadIdx.x] - v;
    if (threadIdx.x == SCAN_B - 1) g_partials[blockIdx.x] = sh[SCAN_B - 1];
}
__global__ void scan_partials_kernel(int nb) {
    __shared__ int sh[512];
    int t = threadIdx.x;
    int v = (t < nb) ? g_partials[t] : 0;
    sh[t] = v;
    __syncthreads();
    #pragma unroll
    for (int off = 1; off < 512; off <<= 1) {
        int tv = 0;
        if (t >= off) tv = sh[t - off];
        __syncthreads();
        sh[t] += tv;
        __syncthreads();
    }
    if (t < nb) g_partials[t] = sh[t] - v;
}
__global__ void scan_add_kernel(int n, int e_cnt) {
    int i = blockIdx.x * SCAN_B + threadIdx.x;
    if (i < n) {
        int r = g_local[i] + g_partials[blockIdx.x];
        g_row_ptr[i] = r;
        g_cursor[i]  = r;
        g_dinv[i] = rsqrtf((float)(g_cnt[i] + 1));
    }
    if (i == 0) g_row_ptr[n] = e_cnt;
}
__global__ void fill_csr_kernel(const int* __restrict__ src,
                                const int* __restrict__ dst, int e_cnt) {
    int e = blockIdx.x * blockDim.x + threadIdx.x;
    if (e < e_cnt) {
        int d = dst[e];
        int pos = atomicAdd(&g_cursor[d], 1);
        g_col[pos] = src[e];
    }
}

// ---------------- prep: W1 -> fragment-packed split bf16; W2 -> padded split ----
__global__ void prep_kernel(const float* __restrict__ W1, const float* __restrict__ W2) {
    int i = blockIdx.x * blockDim.x + threadIdx.x;
    if (i < 32 * 8 * 32) {
        int lane = i & 31;
        int N2   = (i >> 5) & 7;
        int K    = i >> 8;
        int t = lane & 3, g = lane >> 2;
        int k0 = K * 16 + 2 * t;
        int n  = N2 * 16 + g;
        float2 p0 = make_float2(W1[(k0    ) * D_H + n],     W1[(k0 + 1) * D_H + n]);
        float2 p1 = make_float2(W1[(k0 + 8) * D_H + n],     W1[(k0 + 9) * D_H + n]);
        float2 p2 = make_float2(W1[(k0    ) * D_H + n + 8], W1[(k0 + 1) * D_H + n + 8]);
        float2 p3 = make_float2(W1[(k0 + 8) * D_H + n + 8], W1[(k0 + 9) * D_H + n + 8]);
        uint4 h, l;
        h.x = pack_hi(p0); l.x = pack_lo(p0, h.x);
        h.y = pack_hi(p1); l.y = pack_lo(p1, h.y);
        h.z = pack_hi(p2); l.z = pack_lo(p2, h.z);
        h.w = pack_hi(p3); l.w = pack_lo(p3, h.w);
        g_w1f_h[i] = h;
        g_w1f_l[i] = l;
    } else {
        int j = i - 32 * 8 * 32;
        if (j < 128 * 28) {
            int k = j / 28, c = j % 28;
            float2 p;
            p.x = (2 * c     < D_OUT) ? W2[k * D_OUT + 2 * c]     : 0.f;
            p.y = (2 * c + 1 < D_OUT) ? W2[k * D_OUT + 2 * c + 1] : 0.f;
            uint32_t hp = pack_hi(p);
            g_w2h[j] = hp;
            g_w2l[j] = pack_lo(p, hp);
        }
    }
}

// ---------------- GEMM1 (HMMA): h1 = x @ W1  (R13 converged config) -------------
// Block 128x128, 8 warps (4m x 2n), warp tile 32x64, 2 CTAs/SM.
// Sync-free, smem-free; A prefetched one iteration ahead; B hi->lo through
// one 16-reg buffer. bf16x2-packed epilogue.
__global__ __launch_bounds__(256, 2) void gemm1_mma_kernel(const float* __restrict__ A, int M) {
    const int tid  = threadIdx.x;
    const int lane = tid & 31;
    const int wid  = tid >> 5;
    const int wm   = wid >> 1;
    const int wn   = wid & 1;
    const int row0 = blockIdx.x * 128;

    const int fr = row0 + wm * 32 + (lane >> 2);
    const int fc = (lane & 3) * 2;
    const float* pr[2][2];
    bool vr[2][2];
    #pragma unroll
    for (int mt = 0; mt < 2; mt++)
        #pragma unroll
        for (int h = 0; h < 2; h++) {
            int r = fr + mt * 16 + h * 8;
            vr[mt][h] = (r < M);
            pr[mt][h] = A + (size_t)(vr[mt][h] ? r : 0) * D_IN;
        }

    const uint4* bfh = g_w1f_h + (size_t)(wn * 4) * 32 + lane;
    const uint4* bfl = g_w1f_l + (size_t)(wn * 4) * 32 + lane;

    float acc[2][8][4];
    #pragma unroll
    for (int a = 0; a < 2; a++)
        #pragma unroll
        for (int b = 0; b < 8; b++)
            #pragma unroll
            for (int c = 0; c < 4; c++) acc[a][b][c] = 0.f;

    const float2 z2 = make_float2(0.f, 0.f);

    float2 p[2][4];
    #pragma unroll
    for (int mt = 0; mt < 2; mt++) {
        p[mt][0] = vr[mt][0] ? *(const float2*)&pr[mt][0][fc]     : z2;
        p[mt][1] = vr[mt][1] ? *(const float2*)&pr[mt][1][fc]     : z2;
        p[mt][2] = vr[mt][0] ? *(const float2*)&pr[mt][0][fc + 8] : z2;
        p[mt][3] = vr[mt][1] ? *(const float2*)&pr[mt][1][fc + 8] : z2;
    }

    for (int K = 0; K < 32; K++) {
        uint32_t ah[2][4], al[2][4];
        #pragma unroll
        for (int mt = 0; mt < 2; mt++)
            #pragma unroll
            for (int j = 0; j < 4; j++) {
                ah[mt][j] = pack_hi(p[mt][j]);
                al[mt][j] = pack_lo(p[mt][j], ah[mt][j]);
            }
        if (K < 31) {
            const int c = (K + 1) * 16 + fc;
            #pragma unroll
            for (int mt = 0; mt < 2; mt++) {
                p[mt][0] = vr[mt][0] ? *(const float2*)&pr[mt][0][c]     : z2;
                p[mt][1] = vr[mt][1] ? *(const float2*)&pr[mt][1][c]     : z2;
                p[mt][2] = vr[mt][0] ? *(const float2*)&pr[mt][0][c + 8] : z2;
                p[mt][3] = vr[mt][1] ? *(const float2*)&pr[mt][1][c + 8] : z2;
            }
        }

        uint4 q[4];
        #pragma unroll
        for (int j = 0; j < 4; j++) q[j] = bfh[(size_t)(K * 8 + j) * 32];
        #pragma unroll
        for (int j = 0; j < 4; j++) {
            mma_bf16(acc[0][2*j],     ah[0], q[j].x, q[j].y);
            mma_bf16(acc[1][2*j],     ah[1], q[j].x, q[j].y);
            mma_bf16(acc[0][2*j + 1], ah[0], q[j].z, q[j].w);
            mma_bf16(acc[1][2*j + 1], ah[1], q[j].z, q[j].w);
        }
        #pragma unroll
        for (int j = 0; j < 4; j++) {
            mma_bf16(acc[0][2*j],     al[0], q[j].x, q[j].y);
            mma_bf16(acc[1][2*j],     al[1], q[j].x, q[j].y);
            mma_bf16(acc[0][2*j + 1], al[0], q[j].z, q[j].w);
            mma_bf16(acc[1][2*j + 1], al[1], q[j].z, q[j].w);
        }
        #pragma unroll
        for (int j = 0; j < 4; j++) q[j] = bfl[(size_t)(K * 8 + j) * 32];
        #pragma unroll
        for (int j = 0; j < 4; j++) {
            mma_bf16(acc[0][2*j],     ah[0], q[j].x, q[j].y);
            mma_bf16(acc[1][2*j],     ah[1], q[j].x, q[j].y);
            mma_bf16(acc[0][2*j + 1], ah[0], q[j].z, q[j].w);
            mma_bf16(acc[1][2*j + 1], ah[1], q[j].z, q[j].w);
        }
    }

    // epilogue: pack pairs to bf16x2 and store one u32 per (row, n8 tile)
    const int g  = lane >> 2;
    const int tg = lane & 3;
    #pragma unroll
    for (int mt = 0; mt < 2; mt++) {
        #pragma unroll
        for (int nt = 0; nt < 8; nt++) {
            int word = (wn * 4 + (nt >> 1)) * 8 + (nt & 1) * 4 + tg;
            int r0  = row0 + wm * 32 + mt * 16 + g;
            if (r0 < M)
                g_h1b[(size_t)r0 * 64 + word] =
                    pack_hi(make_float2(acc[mt][nt][0], acc[mt][nt][1]));
            int r1 = r0 + 8;
            if (r1 < M)
                g_h1b[(size_t)r1 * 64 + word] =
                    pack_hi(make_float2(acc[mt][nt][2], acc[mt][nt][3]));
        }
    }
}

// ---------------- Aggregation layer 1: two edges per warp-iteration ------------
// Warp = 1 node. Lane l handles edge e + (l>>4); each lane loads uint4 (8 cols).
// Unrolled x2 (4 edges in flight). Epilogue reduces halves via shfl_xor(16).
__global__ void agg1_kernel(const float* __restrict__ b1, int n) {
    int warp = (blockIdx.x * blockDim.x + threadIdx.x) >> 5;
    int lane = threadIdx.x & 31;
    if (warp >= n) return;
    const int node = warp;
    const int start = g_row_ptr[node];
    const int end   = g_row_ptr[node + 1];
    const int half  = lane >> 4;       // 0 or 1
    const int sub   = lane & 15;
    const int wofs  = sub * 4;         // u32 word offset (covers cols sub*8..sub*8+7)

    float a0[8], a1[8];
    #pragma unroll
    for (int i = 0; i < 8; i++) { a0[i] = 0.f; a1[i] = 0.f; }

    int e = start;
    // main loop: 4 edges per iteration (2 per half x 2 unroll)
    for (; e + 4 <= end; e += 4) {
        int s0 = g_col[e + half];
        int s1 = g_col[e + 2 + half];
        float d0 = g_dinv[s0];
        float d1 = g_dinv[s1];
        uint4 w0 = *(const uint4*)&g_h1b[(size_t)s0 * 64 + wofs];
        uint4 w1 = *(const uint4*)&g_h1b[(size_t)s1 * 64 + wofs];
        float2 f;
        f = bf2f(w0.x); a0[0] = fmaf(d0, f.x, a0[0]); a0[1] = fmaf(d0, f.y, a0[1]);
        f = bf2f(w0.y); a0[2] = fmaf(d0, f.x, a0[2]); a0[3] = fmaf(d0, f.y, a0[3]);
        f = bf2f(w0.z); a0[4] = fmaf(d0, f.x, a0[4]); a0[5] = fmaf(d0, f.y, a0[5]);
        f = bf2f(w0.w); a0[6] = fmaf(d0, f.x, a0[6]); a0[7] = fmaf(d0, f.y, a0[7]);
        f = bf2f(w1.x); a1[0] = fmaf(d1, f.x, a1[0]); a1[1] = fmaf(d1, f.y, a1[1]);
        f = bf2f(w1.y); a1[2] = fmaf(d1, f.x, a1[2]); a1[3] = fmaf(d1, f.y, a1[3]);
        f = bf2f(w1.z); a1[4] = fmaf(d1, f.x, a1[4]); a1[5] = fmaf(d1, f.y, a1[5]);
        f = bf2f(w1.w); a1[6] = fmaf(d1, f.x, a1[6]); a1[7] = fmaf(d1, f.y, a1[7]);
    }
    // 2-edge step
    if (e + 2 <= end) {
        int s0 = g_col[e + half];
        float d0 = g_dinv[s0];
        uint4 w0 = *(const uint4*)&g_h1b[(size_t)s0 * 64 + wofs];
        float2 f;
        f = bf2f(w0.x); a0[0] = fmaf(d0, f.x, a0[0]); a0[1] = fmaf(d0, f.y, a0[1]);
        f = bf2f(w0.y); a0[2] = fmaf(d0, f.x, a0[2]); a0[3] = fmaf(d0, f.y, a0[3]);
        f = bf2f(w0.z); a0[4] = fmaf(d0, f.x, a0[4]); a0[5] = fmaf(d0, f.y, a0[5]);
        f = bf2f(w0.w); a0[6] = fmaf(d0, f.x, a0[6]); a0[7] = fmaf(d0, f.y, a0[7]);
        e += 2;
    }
    // final single edge: only half 0 contributes
    if (e < end && half == 0) {
        int s0 = g_col[e];
        float d0 = g_dinv[s0];
        uint4 w0 = *(const uint4*)&g_h1b[(size_t)s0 * 64 + wofs];
        float2 f;
        f = bf2f(w0.x); a0[0] = fmaf(d0, f.x, a0[0]); a0[1] = fmaf(d0, f.y, a0[1]);
        f = bf2f(w0.y); a0[2] = fmaf(d0, f.x, a0[2]); a0[3] = fmaf(d0, f.y, a0[3]);
        f = bf2f(w0.z); a0[4] = fmaf(d0, f.x, a0[4]); a0[5] = fmaf(d0, f.y, a0[5]);
        f = bf2f(w0.w); a0[6] = fmaf(d0, f.x, a0[6]); a0[7] = fmaf(d0, f.y, a0[7]);
    }

    // combine unroll sets + reduce across halves
    float acc[8];
    #pragma unroll
    for (int i = 0; i < 8; i++) {
        float v = a0[i] + a1[i];
        v += __shfl_xor_sync(0xffffffffu, v, 16);
        acc[i] = v;
    }

    // self-loop + bias + relu
    float di = g_dinv[node];
    uint4 ws = *(const uint4*)&g_h1b[(size_t)node * 64 + wofs];
    float4 bb0 = *(const float4*)&b1[sub * 8];
    float4 bb1 = *(const float4*)&b1[sub * 8 + 4];
    float sv[8];
    {
        float2 f;
        f = bf2f(ws.x); sv[0] = f.x; sv[1] = f.y;
        f = bf2f(ws.y); sv[2] = f.x; sv[3] = f.y;
        f = bf2f(ws.z); sv[4] = f.x; sv[5] = f.y;
        f = bf2f(ws.w); sv[6] = f.x; sv[7] = f.y;
    }
    float bbv[8] = {bb0.x, bb0.y, bb0.z, bb0.w, bb1.x, bb1.y, bb1.z, bb1.w};
    float o[8];
    #pragma unroll
    for (int i = 0; i < 8; i++)
        o[i] = fmaxf(fmaf(di, fmaf(di, sv[i], acc[i]), bbv[i]), 0.f);

    // split hi/lo and store: each half writes 2 of the 4 words
    uint32_t hw[4], lw[4];
    #pragma unroll
    for (int i = 0; i < 4; i++) {
        float2 pp = make_float2(o[2 * i], o[2 * i + 1]);
        hw[i] = pack_hi(pp);
        lw[i] = pack_lo(pp, hw[i]);
    }
    int w0i = wofs + half * 2;
    *(uint2*)&g_h1h[(size_t)node * 64 + w0i] = make_uint2(hw[half * 2], hw[half * 2 + 1]);
    *(uint2*)&g_h1l[(size_t)node * 64 + w0i] = make_uint2(lw[half * 2], lw[half * 2 + 1]);
}

// ---------------- GEMM2 (HMMA): h2 = h1a @ W2 -----------------------------------
__global__ __launch_bounds__(256) void gemm2_mma_kernel(int M) {
    __shared__ __align__(16) uint16_t Bh[128 * 56];
    __shared__ __align__(16) uint16_t Bl[128 * 56];
    const int tid  = threadIdx.x;
    const int lane = tid & 31;
    const int wid  = tid >> 5;
    const int row0 = blockIdx.x * 128;

    uint32_t* Bh32 = reinterpret_cast<uint32_t*>(Bh);
    uint32_t* Bl32 = reinterpret_cast<uint32_t*>(Bl);
    for (int idx = tid; idx < 128 * 28; idx += 256) {
        int k = idx / 28, j = idx % 28;
        Bh32[k * 28 + j] = g_w2h[idx];
        Bl32[k * 28 + j] = g_w2l[idx];
    }
    __syncthreads();

    const int r0 = row0 + wid * 16 + (lane >> 2);
    const int r1 = r0 + 8;
    const bool v0 = (r0 < M), v1 = (r1 < M);
    const uint32_t* ph0 = g_h1h + (size_t)(v0 ? r0 : 0) * 64;
    const uint32_t* ph1 = g_h1h + (size_t)(v1 ? r1 : 0) * 64;
    const uint32_t* pl0 = g_h1l + (size_t)(v0 ? r0 : 0) * 64;
    const uint32_t* pl1 = g_h1l + (size_t)(v1 ? r1 : 0) * 64;

    float acc[5][4];
    #pragma unroll
    for (int a = 0; a < 5; a++)
        #pragma unroll
        for (int c = 0; c < 4; c++) acc[a][c] = 0.f;

    #pragma unroll
    for (int kk = 0; kk < 128; kk += 16) {
        const int kw = (kk >> 1) + (lane & 3);
        uint32_t ah[4], al[4];
        ah[0] = v0 ? ph0[kw]     : 0u;
        ah[1] = v1 ? ph1[kw]     : 0u;
        ah[2] = v0 ? ph0[kw + 4] : 0u;
        ah[3] = v1 ? ph1[kw + 4] : 0u;
        al[0] = v0 ? pl0[kw]     : 0u;
        al[1] = v1 ? pl1[kw]     : 0u;
        al[2] = v0 ? pl0[kw + 4] : 0u;
        al[3] = v1 ? pl1[kw + 4] : 0u;
        #pragma unroll
        for (int nt = 0; nt < 5; nt++) {
            uint32_t bh[2], bl[2];
            ldmB56x2(bh, Bh, kk, nt * 8, lane);
            ldmB56x2(bl, Bl, kk, nt * 8, lane);
            mma_bf16(acc[nt], ah, bh[0], bh[1]);
            mma_bf16(acc[nt], ah, bl[0], bl[1]);
            mma_bf16(acc[nt], al, bh[0], bh[1]);
        }
    }

    const int g  = lane >> 2;
    const int tg = lane & 3;
    #pragma unroll
    for (int nt = 0; nt < 5; nt++) {
        int col = nt * 8 + tg * 2;
        if (v0)
            *(float2*)&g_h2[(size_t)r0 * D_OUT + col] = make_float2(acc[nt][0], acc[nt][1]);
        if (v1)
            *(float2*)&g_h2[(size_t)r1 * D_OUT + col] = make_float2(acc[nt][2], acc[nt][3]);
    }
}

// ---------------- Aggregation layer 2 + bias + log_softmax (MLP-4) -------------
__global__ void agg2_kernel(const float* __restrict__ b2, float* __restrict__ out, int n) {
    int warp = (blockIdx.x * blockDim.x + threadIdx.x) >> 5;
    int lane = threadIdx.x & 31;
    if (warp >= n) return;
    const int node = warp;
    const int start = g_row_ptr[node];
    const int end   = g_row_ptr[node + 1];
    const bool hi = (lane < 8);

    float p0 = 0.f, p1 = 0.f, p2 = 0.f, p3 = 0.f;
    float q0 = 0.f, q1 = 0.f, q2 = 0.f, q3 = 0.f;
    int e = start;
    while (e < end && (e & 3)) {
        int s = g_col[e];
        float d = g_dinv[s];
        const float* hp = &g_h2[(size_t)s * D_OUT];
        p0 = fmaf(d, hp[lane], p0);
        if (hi) q0 = fmaf(d, hp[lane + 32], q0);
        e++;
    }
    for (; e + 4 <= end; e += 4) {
        int4 cs = *(const int4*)&g_col[e];
        float d0 = g_dinv[cs.x], d1 = g_dinv[cs.y], d2 = g_dinv[cs.z], d3 = g_dinv[cs.w];
        const float* h0p = &g_h2[(size_t)cs.x * D_OUT];
        const float* h1p = &g_h2[(size_t)cs.y * D_OUT];
        const float* h2p = &g_h2[(size_t)cs.z * D_OUT];
        const float* h3p = &g_h2[(size_t)cs.w * D_OUT];
        p0 = fmaf(d0, h0p[lane], p0); p1 = fmaf(d1, h1p[lane], p1);
        p2 = fmaf(d2, h2p[lane], p2); p3 = fmaf(d3, h3p[lane], p3);
        if (hi) {
            q0 = fmaf(d0, h0p[lane + 32], q0); q1 = fmaf(d1, h1p[lane + 32], q1);
            q2 = fmaf(d2, h2p[lane + 32], q2); q3 = fmaf(d3, h3p[lane + 32], q3);
        }
    }
    for (; e < end; e++) {
        int s = g_col[e];
        float d = g_dinv[s];
        const float* hp = &g_h2[(size_t)s * D_OUT];
        p0 = fmaf(d, hp[lane], p0);
        if (hi) q0 = fmaf(d, hp[lane + 32], q0);
    }
    float acc0 = (p0 + p1) + (p2 + p3);
    float acc1 = (q0 + q1) + (q2 + q3);

    float di = g_dinv[node];
    const float* sp = &g_h2[(size_t)node * D_OUT];
    float v0 = fmaf(di, fmaf(di, sp[lane], acc0), b2[lane]);
    float v1 = 0.f;
    if (hi) v1 = fmaf(di, fmaf(di, sp[lane + 32], acc1), b2[lane + 32]);

    float m = hi ? fmaxf(v0, v1) : v0;
    #pragma unroll
    for (int o = 16; o >= 1; o >>= 1)
        m = fmaxf(m, __shfl_xor_sync(0xffffffffu, m, o));
    float s = expf(v0 - m) + (hi ? expf(v1 - m) : 0.f);
    #pragma unroll
    for (int o = 16; o >= 1; o >>= 1)
        s += __shfl_xor_sync(0xffffffffu, s, o);
    float ls = logf(s);

    out[node * D_OUT + lane] = v0 - m - ls;
    if (hi) out[node * D_OUT + 32 + lane] = v1 - m - ls;
}

// ---------------- launch --------------------------------------------------------
extern "C" void kernel_launch(void* const* d_in, const int* in_sizes, int n_in,
                              void* d_out, int out_size) {
    const float* x   = (const float*)d_in[0];
    const int*   ei  = (const int*)d_in[1];    // edge_index is int32 (JAX x64 disabled)
    const float* W1  = (const float*)d_in[2];
    const float* b1  = (const float*)d_in[3];
    const float* W2  = (const float*)d_in[4];
    const float* b2  = (const float*)d_in[5];
    float* out = (float*)d_out;

    const int n = in_sizes[0] / D_IN;   // 100000
    const int e = in_sizes[1] / 2;      // 1600000
    const int* src = ei;
    const int* dst = ei + e;

    const int nb_scan = (n + SCAN_B - 1) / SCAN_B;

    static cudaStream_t s_csr = nullptr;
    static cudaEvent_t ev_fork = nullptr, ev_join = nullptr;
    if (s_csr == nullptr) {
        cudaStreamCreateWithFlags(&s_csr, cudaStreamNonBlocking);
        cudaEventCreateWithFlags(&ev_fork, cudaEventDisableTiming);
        cudaEventCreateWithFlags(&ev_join, cudaEventDisableTiming);
    }

    cudaEventRecord(ev_fork, 0);
    cudaStreamWaitEvent(s_csr, ev_fork, 0);

    // gemm1 stays 4th launch (ncu profiles that slot)
    prep_kernel<<<(32 * 8 * 32 + 128 * 28 + 255) / 256, 256>>>(W1, W2);          // 1
    zero_cnt_kernel<<<(n + 255) / 256, 256, 0, s_csr>>>(n);                       // 2
    count_kernel<<<(e + 255) / 256, 256, 0, s_csr>>>(dst, e);                     // 3
    gemm1_mma_kernel<<<(n + 127) / 128, 256>>>(x, n);                             // 4
    scan_block_kernel<<<nb_scan, SCAN_B, 0, s_csr>>>(n);                          // 5
    scan_partials_kernel<<<1, 512, 0, s_csr>>>(nb_scan);                          // 6
    scan_add_kernel<<<nb_scan, SCAN_B, 0, s_csr>>>(n, e);                         // 7
    fill_csr_kernel<<<(e + 255) / 256, 256, 0, s_csr>>>(src, dst, e);             // 8
    cudaEventRecord(ev_join, s_csr);

    cudaStreamWaitEvent(0, ev_join, 0);

    agg1_kernel<<<(n * 32 + 255) / 256, 256>>>(b1, n);
    gemm2_mma_kernel<<<(n + 127) / 128, 256>>>(n);
    agg2_kernel<<<(n * 32 + 255) / 256, 256>>>(b2, out, n);
}

// round 17
// speedup vs baseline: 1.1344x; 1.0231x over previous
#include <cuda_runtime.h>
#include <cuda_bf16.h>
#include <math.h>
#include <stdint.h>

#define NMAX 100000
#define EMAX 1600000
#define D_IN 512
#define D_H  128
#define D_OUT 40
#define SCAN_B 512

// ================= scratch (static device globals; no dynamic alloc) ===========
__device__ int      g_cnt[NMAX];
__device__ int      g_local[NMAX];
__device__ int      g_partials[512];
__device__ int      g_row_ptr[NMAX + 1];
__device__ int      g_cursor[NMAX];
__device__ int      g_col[EMAX];
__device__ float    g_dinv[NMAX];
// h1 stored as packed bf16x2 (row = 64 u32 words) — only consumed by agg1
__device__ uint32_t g_h1b[NMAX * 64];
__device__ float    g_h2 [NMAX * D_OUT];
// h1a (post agg+relu) pre-split bf16 hi/lo, packed 2 per u32, row = 64 u32
__device__ uint32_t g_h1h[NMAX * 64];
__device__ uint32_t g_h1l[NMAX * 64];
// W1 split bf16 hi/lo in mma-fragment-packed order:
//   [K=32 k16-blocks][N2=8 n16-blocks][lane=32] uint4
__device__ uint4    g_w1f_h[32 * 8 * 32];
__device__ uint4    g_w1f_l[32 * 8 * 32];
// W2 split bf16 hi/lo, [k=128][n=56 padded] as u32 words [128][28]
__device__ uint32_t g_w2h[128 * 28];
__device__ uint32_t g_w2l[128 * 28];

// ================= small helpers ================================================
__device__ __forceinline__ uint32_t smem_u32(const void* p) {
    uint32_t a;
    asm("{ .reg .u64 t; cvta.to.shared.u64 t, %1; cvt.u32.u64 %0, t; }" : "=r"(a) : "l"(p));
    return a;
}
__device__ __forceinline__ uint32_t pack_hi(float2 p) {
    uint32_t r;
    asm("cvt.rn.bf16x2.f32 %0, %1, %2;" : "=r"(r) : "f"(p.y), "f"(p.x));
    return r;
}
__device__ __forceinline__ uint32_t pack_lo(float2 p, uint32_t h) {
    float fx = __uint_as_float(h << 16);
    float fy = __uint_as_float(h & 0xffff0000u);
    uint32_t r;
    asm("cvt.rn.bf16x2.f32 %0, %1, %2;" : "=r"(r) : "f"(p.y - fy), "f"(p.x - fx));
    return r;
}
__device__ __forceinline__ float2 bf2f(uint32_t u) {
    __nv_bfloat162 h = *reinterpret_cast<__nv_bfloat162*>(&u);
    return __bfloat1622float2(h);
}

// ldmatrix x2 trans (B, [k][n] row-major stride 56; one n8 tile, k16) — gemm2 only
__device__ __forceinline__ void ldmB56x2(uint32_t* d, const uint16_t* sm, int kk, int n0, int lane) {
    uint32_t addr = smem_u32(sm + (kk + (lane & 15)) * 56 + n0);
    asm volatile("ldmatrix.sync.aligned.m8n8.x2.trans.shared.b16 {%0,%1}, [%2];"
                 : "=r"(d[0]), "=r"(d[1]) : "r"(addr) : "memory");
}
// NOT volatile: pure arithmetic; ptxas may pipeline freely.
__device__ __forceinline__ void mma_bf16(float* c, const uint32_t* a, uint32_t b0, uint32_t b1) {
    asm("mma.sync.aligned.m16n8k16.row.col.f32.bf16.bf16.f32 "
        "{%0,%1,%2,%3}, {%4,%5,%6,%7}, {%8,%9}, {%0,%1,%2,%3};"
        : "+f"(c[0]), "+f"(c[1]), "+f"(c[2]), "+f"(c[3])
        : "r"(a[0]), "r"(a[1]), "r"(a[2]), "r"(a[3]), "r"(b0), "r"(b1));
}

// ---------------- degree / CSR build -------------------------------------------
__global__ void zero_cnt_kernel(int n) {
    int i = blockIdx.x * blockDim.x + threadIdx.x;
    if (i < n) g_cnt[i] = 0;
}
__global__ void count_kernel(const int* __restrict__ dst, int e_cnt) {
    int e = blockIdx.x * blockDim.x + threadIdx.x;
    if (e < e_cnt) atomicAdd(&g_cnt[dst[e]], 1);
}
__global__ void scan_block_kernel(int n) {
    __shared__ int sh[SCAN_B];
    int i = blockIdx.x * SCAN_B + threadIdx.x;
    int v = (i < n) ? g_cnt[i] : 0;
    sh[threadIdx.x] = v;
    __syncthreads();
    #pragma unroll
    for (int off = 1; off < SCAN_B; off <<= 1) {
        int t = 0;
        if ((int)threadIdx.x >= off) t = sh[threadIdx.x - off];
        __syncthreads();
        sh[threadIdx.x] += t;
        __syncthreads();
    }
    if (i < n) g_local[i] = sh[threadIdx.x] - v;
    if (threadIdx.x == SCAN_B - 1) g_partials[blockIdx.x] = sh[SCAN_B - 1];
}
__global__ void scan_partials_kernel(int nb) {
    __shared__ int sh[512];
    int t = threadIdx.x;
    int v = (t < nb) ? g_partials[t] : 0;
    sh[t] = v;
    __syncthreads();
    #pragma unroll
    for (int off = 1; off < 512; off <<= 1) {
        int tv = 0;
        if (t >= off) tv = sh[t - off];
        __syncthreads();
        sh[t] += tv;
        __syncthreads();
    }
    if (t < nb) g_partials[t] = sh[t] - v;
}
__global__ void scan_add_kernel(int n, int e_cnt) {
    int i = blockIdx.x * SCAN_B + threadIdx.x;
    if (i < n) {
        int r = g_local[i] + g_partials[blockIdx.x];
        g_row_ptr[i] = r;
        g_cursor[i]  = r;
        g_dinv[i] = rsqrtf((float)(g_cnt[i] + 1));
    }
    if (i == 0) g_row_ptr[n] = e_cnt;
}
__global__ void fill_csr_kernel(const int* __restrict__ src,
                                const int* __restrict__ dst, int e_cnt) {
    int e = blockIdx.x * blockDim.x + threadIdx.x;
    if (e < e_cnt) {
        int d = dst[e];
        int pos = atomicAdd(&g_cursor[d], 1);
        g_col[pos] = src[e];
    }
}

// ---------------- prep: W1 -> fragment-packed split bf16; W2 -> padded split ----
__global__ void prep_kernel(const float* __restrict__ W1, const float* __restrict__ W2) {
    int i = blockIdx.x * blockDim.x + threadIdx.x;
    if (i < 32 * 8 * 32) {
        int lane = i & 31;
        int N2   = (i >> 5) & 7;
        int K    = i >> 8;
        int t = lane & 3, g = lane >> 2;
        int k0 = K * 16 + 2 * t;
        int n  = N2 * 16 + g;
        float2 p0 = make_float2(W1[(k0    ) * D_H + n],     W1[(k0 + 1) * D_H + n]);
        float2 p1 = make_float2(W1[(k0 + 8) * D_H + n],     W1[(k0 + 9) * D_H + n]);
        float2 p2 = make_float2(W1[(k0    ) * D_H + n + 8], W1[(k0 + 1) * D_H + n + 8]);
        float2 p3 = make_float2(W1[(k0 + 8) * D_H + n + 8], W1[(k0 + 9) * D_H + n + 8]);
        uint4 h, l;
        h.x = pack_hi(p0); l.x = pack_lo(p0, h.x);
        h.y = pack_hi(p1); l.y = pack_lo(p1, h.y);
        h.z = pack_hi(p2); l.z = pack_lo(p2, h.z);
        h.w = pack_hi(p3); l.w = pack_lo(p3, h.w);
        g_w1f_h[i] = h;
        g_w1f_l[i] = l;
    } else {
        int j = i - 32 * 8 * 32;
        if (j < 128 * 28) {
            int k = j / 28, c = j % 28;
            float2 p;
            p.x = (2 * c     < D_OUT) ? W2[k * D_OUT + 2 * c]     : 0.f;
            p.y = (2 * c + 1 < D_OUT) ? W2[k * D_OUT + 2 * c + 1] : 0.f;
            uint32_t hp = pack_hi(p);
            g_w2h[j] = hp;
            g_w2l[j] = pack_lo(p, hp);
        }
    }
}

// ---------------- GEMM1 (HMMA): h1 = x @ W1  (R13 converged config) -------------
__global__ __launch_bounds__(256, 2) void gemm1_mma_kernel(const float* __restrict__ A, int M) {
    const int tid  = threadIdx.x;
    const int lane = tid & 31;
    const int wid  = tid >> 5;
    const int wm   = wid >> 1;
    const int wn   = wid & 1;
    const int row0 = blockIdx.x * 128;

    const int fr = row0 + wm * 32 + (lane >> 2);
    const int fc = (lane & 3) * 2;
    const float* pr[2][2];
    bool vr[2][2];
    #pragma unroll
    for (int mt = 0; mt < 2; mt++)
        #pragma unroll
        for (int h = 0; h < 2; h++) {
            int r = fr + mt * 16 + h * 8;
            vr[mt][h] = (r < M);
            pr[mt][h] = A + (size_t)(vr[mt][h] ? r : 0) * D_IN;
        }

    const uint4* bfh = g_w1f_h + (size_t)(wn * 4) * 32 + lane;
    const uint4* bfl = g_w1f_l + (size_t)(wn * 4) * 32 + lane;

    float acc[2][8][4];
    #pragma unroll
    for (int a = 0; a < 2; a++)
        #pragma unroll
        for (int b = 0; b < 8; b++)
            #pragma unroll
            for (int c = 0; c < 4; c++) acc[a][b][c] = 0.f;

    const float2 z2 = make_float2(0.f, 0.f);

    float2 p[2][4];
    #pragma unroll
    for (int mt = 0; mt < 2; mt++) {
        p[mt][0] = vr[mt][0] ? *(const float2*)&pr[mt][0][fc]     : z2;
        p[mt][1] = vr[mt][1] ? *(const float2*)&pr[mt][1][fc]     : z2;
        p[mt][2] = vr[mt][0] ? *(const float2*)&pr[mt][0][fc + 8] : z2;
        p[mt][3] = vr[mt][1] ? *(const float2*)&pr[mt][1][fc + 8] : z2;
    }

    for (int K = 0; K < 32; K++) {
        uint32_t ah[2][4], al[2][4];
        #pragma unroll
        for (int mt = 0; mt < 2; mt++)
            #pragma unroll
            for (int j = 0; j < 4; j++) {
                ah[mt][j] = pack_hi(p[mt][j]);
                al[mt][j] = pack_lo(p[mt][j], ah[mt][j]);
            }
        if (K < 31) {
            const int c = (K + 1) * 16 + fc;
            #pragma unroll
            for (int mt = 0; mt < 2; mt++) {
                p[mt][0] = vr[mt][0] ? *(const float2*)&pr[mt][0][c]     : z2;
                p[mt][1] = vr[mt][1] ? *(const float2*)&pr[mt][1][c]     : z2;
                p[mt][2] = vr[mt][0] ? *(const float2*)&pr[mt][0][c + 8] : z2;
                p[mt][3] = vr[mt][1] ? *(const float2*)&pr[mt][1][c + 8] : z2;
            }
        }

        uint4 q[4];
        #pragma unroll
        for (int j = 0; j < 4; j++) q[j] = bfh[(size_t)(K * 8 + j) * 32];
        #pragma unroll
        for (int j = 0; j < 4; j++) {
            mma_bf16(acc[0][2*j],     ah[0], q[j].x, q[j].y);
            mma_bf16(acc[1][2*j],     ah[1], q[j].x, q[j].y);
            mma_bf16(acc[0][2*j + 1], ah[0], q[j].z, q[j].w);
            mma_bf16(acc[1][2*j + 1], ah[1], q[j].z, q[j].w);
        }
        #pragma unroll
        for (int j = 0; j < 4; j++) {
            mma_bf16(acc[0][2*j],     al[0], q[j].x, q[j].y);
            mma_bf16(acc[1][2*j],     al[1], q[j].x, q[j].y);
            mma_bf16(acc[0][2*j + 1], al[0], q[j].z, q[j].w);
            mma_bf16(acc[1][2*j + 1], al[1], q[j].z, q[j].w);
        }
        #pragma unroll
        for (int j = 0; j < 4; j++) q[j] = bfl[(size_t)(K * 8 + j) * 32];
        #pragma unroll
        for (int j = 0; j < 4; j++) {
            mma_bf16(acc[0][2*j],     ah[0], q[j].x, q[j].y);
            mma_bf16(acc[1][2*j],     ah[1], q[j].x, q[j].y);
            mma_bf16(acc[0][2*j + 1], ah[0], q[j].z, q[j].w);
            mma_bf16(acc[1][2*j + 1], ah[1], q[j].z, q[j].w);
        }
    }

    // epilogue: pack pairs to bf16x2 and store one u32 per (row, n8 tile)
    const int g  = lane >> 2;
    const int tg = lane & 3;
    #pragma unroll
    for (int mt = 0; mt < 2; mt++) {
        #pragma unroll
        for (int nt = 0; nt < 8; nt++) {
            int word = (wn * 4 + (nt >> 1)) * 8 + (nt & 1) * 4 + tg;
            int r0  = row0 + wm * 32 + mt * 16 + g;
            if (r0 < M)
                g_h1b[(size_t)r0 * 64 + word] =
                    pack_hi(make_float2(acc[mt][nt][0], acc[mt][nt][1]));
            int r1 = r0 + 8;
            if (r1 < M)
                g_h1b[(size_t)r1 * 64 + word] =
                    pack_hi(make_float2(acc[mt][nt][2], acc[mt][nt][3]));
        }
    }
}

// ---------------- Aggregation layer 1: two edges per warp-iteration ------------
__global__ void agg1_kernel(const float* __restrict__ b1, int n) {
    int warp = (blockIdx.x * blockDim.x + threadIdx.x) >> 5;
    int lane = threadIdx.x & 31;
    if (warp >= n) return;
    const int node = warp;
    const int start = g_row_ptr[node];
    const int end   = g_row_ptr[node + 1];
    const int half  = lane >> 4;       // 0 or 1
    const int sub   = lane & 15;
    const int wofs  = sub * 4;         // u32 word offset (covers cols sub*8..sub*8+7)

    float a0[8], a1[8];
    #pragma unroll
    for (int i = 0; i < 8; i++) { a0[i] = 0.f; a1[i] = 0.f; }

    int e = start;
    for (; e + 4 <= end; e += 4) {
        int s0 = g_col[e + half];
        int s1 = g_col[e + 2 + half];
        float d0 = g_dinv[s0];
        float d1 = g_dinv[s1];
        uint4 w0 = *(const uint4*)&g_h1b[(size_t)s0 * 64 + wofs];
        uint4 w1 = *(const uint4*)&g_h1b[(size_t)s1 * 64 + wofs];
        float2 f;
        f = bf2f(w0.x); a0[0] = fmaf(d0, f.x, a0[0]); a0[1] = fmaf(d0, f.y, a0[1]);
        f = bf2f(w0.y); a0[2] = fmaf(d0, f.x, a0[2]); a0[3] = fmaf(d0, f.y, a0[3]);
        f = bf2f(w0.z); a0[4] = fmaf(d0, f.x, a0[4]); a0[5] = fmaf(d0, f.y, a0[5]);
        f = bf2f(w0.w); a0[6] = fmaf(d0, f.x, a0[6]); a0[7] = fmaf(d0, f.y, a0[7]);
        f = bf2f(w1.x); a1[0] = fmaf(d1, f.x, a1[0]); a1[1] = fmaf(d1, f.y, a1[1]);
        f = bf2f(w1.y); a1[2] = fmaf(d1, f.x, a1[2]); a1[3] = fmaf(d1, f.y, a1[3]);
        f = bf2f(w1.z); a1[4] = fmaf(d1, f.x, a1[4]); a1[5] = fmaf(d1, f.y, a1[5]);
        f = bf2f(w1.w); a1[6] = fmaf(d1, f.x, a1[6]); a1[7] = fmaf(d1, f.y, a1[7]);
    }
    if (e + 2 <= end) {
        int s0 = g_col[e + half];
        float d0 = g_dinv[s0];
        uint4 w0 = *(const uint4*)&g_h1b[(size_t)s0 * 64 + wofs];
        float2 f;
        f = bf2f(w0.x); a0[0] = fmaf(d0, f.x, a0[0]); a0[1] = fmaf(d0, f.y, a0[1]);
        f = bf2f(w0.y); a0[2] = fmaf(d0, f.x, a0[2]); a0[3] = fmaf(d0, f.y, a0[3]);
        f = bf2f(w0.z); a0[4] = fmaf(d0, f.x, a0[4]); a0[5] = fmaf(d0, f.y, a0[5]);
        f = bf2f(w0.w); a0[6] = fmaf(d0, f.x, a0[6]); a0[7] = fmaf(d0, f.y, a0[7]);
        e += 2;
    }
    if (e < end && half == 0) {
        int s0 = g_col[e];
        float d0 = g_dinv[s0];
        uint4 w0 = *(const uint4*)&g_h1b[(size_t)s0 * 64 + wofs];
        float2 f;
        f = bf2f(w0.x); a0[0] = fmaf(d0, f.x, a0[0]); a0[1] = fmaf(d0, f.y, a0[1]);
        f = bf2f(w0.y); a0[2] = fmaf(d0, f.x, a0[2]); a0[3] = fmaf(d0, f.y, a0[3]);
        f = bf2f(w0.z); a0[4] = fmaf(d0, f.x, a0[4]); a0[5] = fmaf(d0, f.y, a0[5]);
        f = bf2f(w0.w); a0[6] = fmaf(d0, f.x, a0[6]); a0[7] = fmaf(d0, f.y, a0[7]);
    }

    float acc[8];
    #pragma unroll
    for (int i = 0; i < 8; i++) {
        float v = a0[i] + a1[i];
        v += __shfl_xor_sync(0xffffffffu, v, 16);
        acc[i] = v;
    }

    float di = g_dinv[node];
    uint4 ws = *(const uint4*)&g_h1b[(size_t)node * 64 + wofs];
    float4 bb0 = *(const float4*)&b1[sub * 8];
    float4 bb1 = *(const float4*)&b1[sub * 8 + 4];
    float sv[8];
    {
        float2 f;
        f = bf2f(ws.x); sv[0] = f.x; sv[1] = f.y;
        f = bf2f(ws.y); sv[2] = f.x; sv[3] = f.y;
        f = bf2f(ws.z); sv[4] = f.x; sv[5] = f.y;
        f = bf2f(ws.w); sv[6] = f.x; sv[7] = f.y;
    }
    float bbv[8] = {bb0.x, bb0.y, bb0.z, bb0.w, bb1.x, bb1.y, bb1.z, bb1.w};
    float o[8];
    #pragma unroll
    for (int i = 0; i < 8; i++)
        o[i] = fmaxf(fmaf(di, fmaf(di, sv[i], acc[i]), bbv[i]), 0.f);

    uint32_t hw[4], lw[4];
    #pragma unroll
    for (int i = 0; i < 4; i++) {
        float2 pp = make_float2(o[2 * i], o[2 * i + 1]);
        hw[i] = pack_hi(pp);
        lw[i] = pack_lo(pp, hw[i]);
    }
    int w0i = wofs + half * 2;
    *(uint2*)&g_h1h[(size_t)node * 64 + w0i] = make_uint2(hw[half * 2], hw[half * 2 + 1]);
    *(uint2*)&g_h1l[(size_t)node * 64 + w0i] = make_uint2(lw[half * 2], lw[half * 2 + 1]);
}

// ---------------- GEMM2 (HMMA): h2 = h1a @ W2 -----------------------------------
__global__ __launch_bounds__(256) void gemm2_mma_kernel(int M) {
    __shared__ __align__(16) uint16_t Bh[128 * 56];
    __shared__ __align__(16) uint16_t Bl[128 * 56];
    const int tid  = threadIdx.x;
    const int lane = tid & 31;
    const int wid  = tid >> 5;
    const int row0 = blockIdx.x * 128;

    uint32_t* Bh32 = reinterpret_cast<uint32_t*>(Bh);
    uint32_t* Bl32 = reinterpret_cast<uint32_t*>(Bl);
    for (int idx = tid; idx < 128 * 28; idx += 256) {
        int k = idx / 28, j = idx % 28;
        Bh32[k * 28 + j] = g_w2h[idx];
        Bl32[k * 28 + j] = g_w2l[idx];
    }
    __syncthreads();

    const int r0 = row0 + wid * 16 + (lane >> 2);
    const int r1 = r0 + 8;
    const bool v0 = (r0 < M), v1 = (r1 < M);
    const uint32_t* ph0 = g_h1h + (size_t)(v0 ? r0 : 0) * 64;
    const uint32_t* ph1 = g_h1h + (size_t)(v1 ? r1 : 0) * 64;
    const uint32_t* pl0 = g_h1l + (size_t)(v0 ? r0 : 0) * 64;
    const uint32_t* pl1 = g_h1l + (size_t)(v1 ? r1 : 0) * 64;

    float acc[5][4];
    #pragma unroll
    for (int a = 0; a < 5; a++)
        #pragma unroll
        for (int c = 0; c < 4; c++) acc[a][c] = 0.f;

    #pragma unroll
    for (int kk = 0; kk < 128; kk += 16) {
        const int kw = (kk >> 1) + (lane & 3);
        uint32_t ah[4], al[4];
        ah[0] = v0 ? ph0[kw]     : 0u;
        ah[1] = v1 ? ph1[kw]     : 0u;
        ah[2] = v0 ? ph0[kw + 4] : 0u;
        ah[3] = v1 ? ph1[kw + 4] : 0u;
        al[0] = v0 ? pl0[kw]     : 0u;
        al[1] = v1 ? pl1[kw]     : 0u;
        al[2] = v0 ? pl0[kw + 4] : 0u;
        al[3] = v1 ? pl1[kw + 4] : 0u;
        #pragma unroll
        for (int nt = 0; nt < 5; nt++) {
            uint32_t bh[2], bl[2];
            ldmB56x2(bh, Bh, kk, nt * 8, lane);
            ldmB56x2(bl, Bl, kk, nt * 8, lane);
            mma_bf16(acc[nt], ah, bh[0], bh[1]);
            mma_bf16(acc[nt], ah, bl[0], bl[1]);
            mma_bf16(acc[nt], al, bh[0], bh[1]);
        }
    }

    const int g  = lane >> 2;
    const int tg = lane & 3;
    #pragma unroll
    for (int nt = 0; nt < 5; nt++) {
        int col = nt * 8 + tg * 2;
        if (v0)
            *(float2*)&g_h2[(size_t)r0 * D_OUT + col] = make_float2(acc[nt][0], acc[nt][1]);
        if (v1)
            *(float2*)&g_h2[(size_t)r1 * D_OUT + col] = make_float2(acc[nt][2], acc[nt][3]);
    }
}

// ---------------- Aggregation layer 2: two edges/iter + log_softmax ------------
// Warp = 1 node. half = lane>>4 picks the edge; lanes sub<10 each load one
// float4 (10 x 16B = 160B = exact h2 row). Unrolled x2. Cross-half reduce via
// shfl_xor(16); softmax reduces over half-0 active lanes.
__global__ void agg2_kernel(const float* __restrict__ b2, float* __restrict__ out, int n) {
    int warp = (blockIdx.x * blockDim.x + threadIdx.x) >> 5;
    int lane = threadIdx.x & 31;
    if (warp >= n) return;
    const int node = warp;
    const int start = g_row_ptr[node];
    const int end   = g_row_ptr[node + 1];
    const int half  = lane >> 4;
    const int sub   = lane & 15;
    const bool act  = (sub < 10);
    const int co    = sub * 4;

    float a0[4] = {0.f, 0.f, 0.f, 0.f};
    float a1[4] = {0.f, 0.f, 0.f, 0.f};

    int e = start;
    for (; e + 4 <= end; e += 4) {
        int s0 = g_col[e + half];
        int s1 = g_col[e + 2 + half];
        float d0 = g_dinv[s0];
        float d1 = g_dinv[s1];
        if (act) {
            float4 v0 = *(const float4*)&g_h2[(size_t)s0 * D_OUT + co];
            float4 v1 = *(const float4*)&g_h2[(size_t)s1 * D_OUT + co];
            a0[0] = fmaf(d0, v0.x, a0[0]); a0[1] = fmaf(d0, v0.y, a0[1]);
            a0[2] = fmaf(d0, v0.z, a0[2]); a0[3] = fmaf(d0, v0.w, a0[3]);
            a1[0] = fmaf(d1, v1.x, a1[0]); a1[1] = fmaf(d1, v1.y, a1[1]);
            a1[2] = fmaf(d1, v1.z, a1[2]); a1[3] = fmaf(d1, v1.w, a1[3]);
        }
    }
    if (e + 2 <= end) {
        int s0 = g_col[e + half];
        float d0 = g_dinv[s0];
        if (act) {
            float4 v0 = *(const float4*)&g_h2[(size_t)s0 * D_OUT + co];
            a0[0] = fmaf(d0, v0.x, a0[0]); a0[1] = fmaf(d0, v0.y, a0[1]);
            a0[2] = fmaf(d0, v0.z, a0[2]); a0[3] = fmaf(d0, v0.w, a0[3]);
        }
        e += 2;
    }
    if (e < end && half == 0) {
        int s0 = g_col[e];
        float d0 = g_dinv[s0];
        if (act) {
            float4 v0 = *(const float4*)&g_h2[(size_t)s0 * D_OUT + co];
            a0[0] = fmaf(d0, v0.x, a0[0]); a0[1] = fmaf(d0, v0.y, a0[1]);
            a0[2] = fmaf(d0, v0.z, a0[2]); a0[3] = fmaf(d0, v0.w, a0[3]);
        }
    }

    float acc[4];
    #pragma unroll
    for (int j = 0; j < 4; j++) {
        float v = a0[j] + a1[j];
        v += __shfl_xor_sync(0xffffffffu, v, 16);
        acc[j] = v;
    }

    // self-loop + bias
    float di = g_dinv[node];
    float4 sv = make_float4(0.f, 0.f, 0.f, 0.f);
    float4 bb = make_float4(0.f, 0.f, 0.f, 0.f);
    if (act) {
        sv = *(const float4*)&g_h2[(size_t)node * D_OUT + co];
        bb = *(const float4*)&b2[co];
    }
    float v[4];
    v[0] = fmaf(di, fmaf(di, sv.x, acc[0]), bb.x);
    v[1] = fmaf(di, fmaf(di, sv.y, acc[1]), bb.y);
    v[2] = fmaf(di, fmaf(di, sv.z, acc[2]), bb.z);
    v[3] = fmaf(di, fmaf(di, sv.w, acc[3]), bb.w);

    // log_softmax over 40 values (half-0 active lanes own them)
    const bool red = (half == 0) && act;
    float m = red ? fmaxf(fmaxf(v[0], v[1]), fmaxf(v[2], v[3])) : -1e30f;
    #pragma unroll
    for (int o = 16; o >= 1; o >>= 1)
        m = fmaxf(m, __shfl_xor_sync(0xffffffffu, m, o));
    float s = red ? (expf(v[0] - m) + expf(v[1] - m) + expf(v[2] - m) + expf(v[3] - m)) : 0.f;
    #pragma unroll
    for (int o = 16; o >= 1; o >>= 1)
        s += __shfl_xor_sync(0xffffffffu, s, o);
    float ls = logf(s);

    if (red) {
        float4 o4 = make_float4(v[0] - m - ls, v[1] - m - ls, v[2] - m - ls, v[3] - m - ls);
        *(float4*)&out[(size_t)node * D_OUT + co] = o4;
    }
}

// ---------------- launch --------------------------------------------------------
extern "C" void kernel_launch(void* const* d_in, const int* in_sizes, int n_in,
                              void* d_out, int out_size) {
    const float* x   = (const float*)d_in[0];
    const int*   ei  = (const int*)d_in[1];    // edge_index is int32 (JAX x64 disabled)
    const float* W1  = (const float*)d_in[2];
    const float* b1  = (const float*)d_in[3];
    const float* W2  = (const float*)d_in[4];
    const float* b2  = (const float*)d_in[5];
    float* out = (float*)d_out;

    const int n = in_sizes[0] / D_IN;   // 100000
    const int e = in_sizes[1] / 2;      // 1600000
    const int* src = ei;
    const int* dst = ei + e;

    const int nb_scan = (n + SCAN_B - 1) / SCAN_B;

    static cudaStream_t s_csr = nullptr;
    static cudaEvent_t ev_fork = nullptr, ev_join = nullptr;
    if (s_csr == nullptr) {
        cudaStreamCreateWithFlags(&s_csr, cudaStreamNonBlocking);
        cudaEventCreateWithFlags(&ev_fork, cudaEventDisableTiming);
        cudaEventCreateWithFlags(&ev_join, cudaEventDisableTiming);
    }

    cudaEventRecord(ev_fork, 0);
    cudaStreamWaitEvent(s_csr, ev_fork, 0);

    // gemm1 stays 4th launch (ncu profiles that slot)
    prep_kernel<<<(32 * 8 * 32 + 128 * 28 + 255) / 256, 256>>>(W1, W2);          // 1
    zero_cnt_kernel<<<(n + 255) / 256, 256, 0, s_csr>>>(n);                       // 2
    count_kernel<<<(e + 255) / 256, 256, 0, s_csr>>>(dst, e);                     // 3
    gemm1_mma_kernel<<<(n + 127) / 128, 256>>>(x, n);                             // 4
    scan_block_kernel<<<nb_scan, SCAN_B, 0, s_csr>>>(n);                          // 5
    scan_partials_kernel<<<1, 512, 0, s_csr>>>(nb_scan);                          // 6
    scan_add_kernel<<<nb_scan, SCAN_B, 0, s_csr>>>(n, e);                         // 7
    fill_csr_kernel<<<(e + 255) / 256, 256, 0, s_csr>>>(src, dst, e);             // 8
    cudaEventRecord(ev_join, s_csr);

    cudaStreamWaitEvent(0, ev_join, 0);

    agg1_kernel<<<(n * 32 + 255) / 256, 256>>>(b1, n);
    gemm2_mma_kernel<<<(n + 127) / 128, 256>>>(n);
    agg2_kernel<<<(n * 32 + 255) / 256, 256>>>(b2, out, n);
}